// round 1
// baseline (speedup 1.0000x reference)
#include <cuda_runtime.h>
#include <cstdint>

#define NSUB 8
#define BTOK 4096
#define DIN  512
#define DFF  2048
#define DOUT 512

// ---- device-global scratch (allocation-free requirement) ----
__device__ int   g_tok[BTOK];          // token ids, sorted by expert
__device__ int   g_off[NSUB + 1];      // expert offsets into g_tok
__device__ float g_h[(size_t)BTOK * DFF]; // intermediate h (compact order), 33.5 MB

// ---------------------------------------------------------------------------
// Routing: histogram + prefix + scatter. One block; deterministic output set
// (within-expert order is atomics-dependent but results are order-invariant).
// ---------------------------------------------------------------------------
__global__ void route_kernel(const int* __restrict__ groups)
{
    __shared__ int s_cnt[NSUB];
    __shared__ int s_cur[NSUB];
    const int tid = threadIdx.x;
    if (tid < NSUB) s_cnt[tid] = 0;
    __syncthreads();
    for (int b = tid; b < BTOK; b += blockDim.x)
        atomicAdd(&s_cnt[groups[2 * b]], 1);
    __syncthreads();
    if (tid == 0) {
        int off = 0;
        for (int e = 0; e < NSUB; ++e) {
            g_off[e] = off;
            s_cur[e] = off;
            off += s_cnt[e];
        }
        g_off[NSUB] = off;
    }
    __syncthreads();
    for (int b = tid; b < BTOK; b += blockDim.x) {
        int e = groups[2 * b];
        int pos = atomicAdd(&s_cur[e], 1);
        g_tok[pos] = b;
    }
}

// ---------------------------------------------------------------------------
// Tiled fp32 GEMM, 128x128x16, 256 threads, 8x8 per thread, double-buffered.
// FIRST:  h = relu(x[gather] @ W1[e] + b1[e])  -> g_h (compact rows)
// !FIRST: y = h @ W2[e] + b2[e]                -> out (scatter rows by token)
// ---------------------------------------------------------------------------
template <bool FIRST>
__global__ __launch_bounds__(256, 2)
void ffn_gemm_kernel(const float* __restrict__ X,
                     const float* __restrict__ W,
                     const float* __restrict__ bias,
                     float* __restrict__ Y)
{
    constexpr int K  = FIRST ? DIN : DFF;
    constexpr int N  = FIRST ? DFF : DOUT;
    constexpr int BM = 128, BN = 128, BK = 16;
    constexpr int KT = K / BK;

    const int e   = blockIdx.z;
    const int off = g_off[e];
    const int cnt = g_off[e + 1] - off;
    const int m0  = blockIdx.y * BM;
    if (m0 >= cnt) return;                 // empty tile for this expert
    const int n0  = blockIdx.x * BN;

    __shared__ float As[2][BK][BM];        // [k][m] (transposed for M-contig reads)
    __shared__ float Bs[2][BK][BN];        // [k][n]

    const int tid  = threadIdx.x;

    // ---- A global-load mapping: one row per thread-pair, 2 float4 along K
    const int arow = tid >> 1;             // 0..127
    const int acol = (tid & 1) * 8;        // 0 or 8
    const float* Ap;
    {
        const int r  = m0 + arow;
        const int rr = (r < cnt) ? r : 0;  // clamp: OOB rows read valid data, writes masked
        if (FIRST)
            Ap = X + (size_t)g_tok[off + rr] * K + acol;
        else
            Ap = g_h + (size_t)(off + rr) * K + acol;
    }

    // ---- B global-load mapping: one k-row per 16 threads, 2 float4 along N (coalesced)
    const int bkr  = tid >> 4;             // 0..15
    const int bcol = (tid & 15) * 8;       // 0..120
    const float* Bp = W + (size_t)e * K * N + (size_t)bkr * N + n0 + bcol;

    const int tx = tid & 15;               // col group
    const int ty = tid >> 4;               // row group

    float4 a0n, a1n, b0n, b1n;

    // ---- stage 0 ----
    a0n = *(const float4*)(Ap);
    a1n = *(const float4*)(Ap + 4);
    b0n = *(const float4*)(Bp);
    b1n = *(const float4*)(Bp + 4);
    As[0][acol + 0][arow] = a0n.x;
    As[0][acol + 1][arow] = a0n.y;
    As[0][acol + 2][arow] = a0n.z;
    As[0][acol + 3][arow] = a0n.w;
    As[0][acol + 4][arow] = a1n.x;
    As[0][acol + 5][arow] = a1n.y;
    As[0][acol + 6][arow] = a1n.z;
    As[0][acol + 7][arow] = a1n.w;
    *(float4*)&Bs[0][bkr][bcol]     = b0n;
    *(float4*)&Bs[0][bkr][bcol + 4] = b1n;
    __syncthreads();

    float acc[8][8];
    #pragma unroll
    for (int i = 0; i < 8; ++i)
        #pragma unroll
        for (int j = 0; j < 8; ++j)
            acc[i][j] = 0.0f;

    #pragma unroll 1
    for (int kt = 0; kt < KT; ++kt) {
        const int  cur       = kt & 1;
        const bool have_next = (kt + 1 < KT);
        if (have_next) {
            const float* ap = Ap + (kt + 1) * BK;
            a0n = *(const float4*)(ap);
            a1n = *(const float4*)(ap + 4);
            const float* bp = Bp + (size_t)(kt + 1) * BK * N;
            b0n = *(const float4*)(bp);
            b1n = *(const float4*)(bp + 4);
        }
        #pragma unroll
        for (int k = 0; k < BK; ++k) {
            float a[8], b[8];
            // split 4+4 fragments: conflict-free LDS.128 phases
            *(float4*)&a[0] = *(const float4*)&As[cur][k][ty * 4];
            *(float4*)&a[4] = *(const float4*)&As[cur][k][ty * 4 + 64];
            *(float4*)&b[0] = *(const float4*)&Bs[cur][k][tx * 4];
            *(float4*)&b[4] = *(const float4*)&Bs[cur][k][tx * 4 + 64];
            #pragma unroll
            for (int i = 0; i < 8; ++i)
                #pragma unroll
                for (int j = 0; j < 8; ++j)
                    acc[i][j] = fmaf(a[i], b[j], acc[i][j]);
        }
        if (have_next) {
            const int nb = cur ^ 1;
            As[nb][acol + 0][arow] = a0n.x;
            As[nb][acol + 1][arow] = a0n.y;
            As[nb][acol + 2][arow] = a0n.z;
            As[nb][acol + 3][arow] = a0n.w;
            As[nb][acol + 4][arow] = a1n.x;
            As[nb][acol + 5][arow] = a1n.y;
            As[nb][acol + 6][arow] = a1n.z;
            As[nb][acol + 7][arow] = a1n.w;
            *(float4*)&Bs[nb][bkr][bcol]     = b0n;
            *(float4*)&Bs[nb][bkr][bcol + 4] = b1n;
        }
        __syncthreads();
    }

    // ---- epilogue: bias (+relu for FIRST), masked row writes ----
    const float* bv = bias + (size_t)e * N + n0;
    float bb[8];
    *(float4*)&bb[0] = *(const float4*)(bv + tx * 4);
    *(float4*)&bb[4] = *(const float4*)(bv + tx * 4 + 64);

    #pragma unroll
    for (int i = 0; i < 8; ++i) {
        const int mr = (i < 4) ? (ty * 4 + i) : (64 + ty * 4 + (i - 4));
        const int rm = m0 + mr;
        if (rm >= cnt) continue;
        float o[8];
        #pragma unroll
        for (int j = 0; j < 8; ++j) {
            float v = acc[i][j] + bb[j];
            if (FIRST) v = fmaxf(v, 0.0f);
            o[j] = v;
        }
        float* dst;
        if (FIRST)
            dst = g_h + (size_t)(off + rm) * N + n0;
        else
            dst = Y + (size_t)g_tok[off + rm] * N + n0;
        *(float4*)(dst + tx * 4)      = *(float4*)&o[0];
        *(float4*)(dst + tx * 4 + 64) = *(float4*)&o[4];
    }
}

// ---------------------------------------------------------------------------
// kernel_launch: route -> GEMM1(+relu) -> GEMM2(scatter). Graph-capturable:
// kernel launches only, no allocs, no syncs.
// Input order (metadata): x, groups, W1, b1, W2, b2. Output: float [4096,512].
// ---------------------------------------------------------------------------
extern "C" void kernel_launch(void* const* d_in, const int* in_sizes, int n_in,
                              void* d_out, int out_size)
{
    const float* x      = (const float*)d_in[0];
    const int*   groups = (const int*)  d_in[1];
    const float* W1     = (const float*)d_in[2];
    const float* b1     = (const float*)d_in[3];
    const float* W2     = (const float*)d_in[4];
    const float* b2     = (const float*)d_in[5];
    float*       out    = (float*)d_out;

    route_kernel<<<1, 512>>>(groups);
    // worst-case grids (counts unknown host-side under graph capture);
    // empty tiles early-exit on g_off.
    ffn_gemm_kernel<true ><<<dim3(DFF  / 128, BTOK / 128, NSUB), 256>>>(x,       W1, b1, nullptr);
    ffn_gemm_kernel<false><<<dim3(DOUT / 128, BTOK / 128, NSUB), 256>>>(nullptr, W2, b2, out);
}

// round 5
// speedup vs baseline: 2.9902x; 2.9902x over previous
#include <cuda_runtime.h>
#include <cstdint>

#define NSUB 8
#define BTOK 4096
#define DIN  512
#define DFF  2048
#define DOUT 512

// ---- device-global scratch ----
__device__ int   g_tok[BTOK];
__device__ int   g_off[NSUB + 1];
__device__ float g_h[(size_t)BTOK * DFF];   // intermediate h, compact rows

// ===========================================================================
// Routing
// ===========================================================================
__global__ void route_kernel(const int* __restrict__ groups)
{
    __shared__ int s_cnt[NSUB];
    __shared__ int s_cur[NSUB];
    const int tid = threadIdx.x;
    if (tid < NSUB) s_cnt[tid] = 0;
    __syncthreads();
    for (int b = tid; b < BTOK; b += blockDim.x)
        atomicAdd(&s_cnt[groups[2 * b]], 1);
    __syncthreads();
    if (tid == 0) {
        int off = 0;
        for (int e = 0; e < NSUB; ++e) { g_off[e] = off; s_cur[e] = off; off += s_cnt[e]; }
        g_off[NSUB] = off;
    }
    __syncthreads();
    for (int b = tid; b < BTOK; b += blockDim.x) {
        int e = groups[2 * b];
        int pos = atomicAdd(&s_cur[e], 1);
        g_tok[pos] = b;
    }
}

// ===========================================================================
// helpers
// ===========================================================================
__device__ __forceinline__ uint32_t f2tf(float x) {
    uint32_t u;
    asm("cvt.rna.tf32.f32 %0, %1;" : "=r"(u) : "f"(x));
    return u;
}

__device__ __forceinline__ void mma8(float* c, const uint32_t* a, const uint32_t* b) {
    asm volatile(
        "mma.sync.aligned.m16n8k8.row.col.f32.tf32.tf32.f32 "
        "{%0,%1,%2,%3}, {%4,%5,%6,%7}, {%8,%9}, {%0,%1,%2,%3};"
        : "+f"(c[0]), "+f"(c[1]), "+f"(c[2]), "+f"(c[3])
        : "r"(a[0]), "r"(a[1]), "r"(a[2]), "r"(a[3]), "r"(b[0]), "r"(b[1]));
}

// ===========================================================================
// tf32 mma.sync GEMM: 128x128 tile, BK=32, single smem stage + register
// prefetch (dynamic smem kept under 48KB -> NO cudaFuncSetAttribute needed).
//   FIRST:  h = relu(x[gather] @ W1[e] + b1)  -> g_h (compact rows)
//   !FIRST: y = h @ W2[e] + b2                -> out (scatter by token)
// Smem: stage (32KB): A [128 rows][32 f] swizzled | B [32 k][128 f] swizzled
//       epilogue staging reuses smem: 64 rows x 132 floats (33792 B max)
// ===========================================================================
template <int K, int NTOT, bool FIRST>
__global__ __launch_bounds__(256)
void moe_mma_gemm(const float* __restrict__ X,
                  const float* __restrict__ W,
                  const float* __restrict__ bias,
                  float* __restrict__ Y)
{
    constexpr int KT = K / 32;

    const int e   = blockIdx.z;
    const int off = g_off[e];
    const int cnt = g_off[e + 1] - off;
    const int m0  = blockIdx.y * 128;
    if (m0 >= cnt) return;
    const int n0  = blockIdx.x * 128;

    extern __shared__ char sm[];

    const int tid = threadIdx.x;
    const int wid = tid >> 5, l = tid & 31;
    const int g = l >> 2, tig = l & 3;
    const int wm = wid & 3;          // m offset: wm*32
    const int wn = wid >> 2;         // n offset: wn*64

    // ---- loader mapping: 256 threads, each 4 x 16B for A and B per chunk ----
    const int lr = tid >> 3;         // 0..31
    const int lc = tid & 7;          // 0..7

    const float* aptr[4];
    #pragma unroll
    for (int p = 0; p < 4; ++p) {
        int r  = m0 + lr + 32 * p;
        int rr = (r < cnt) ? r : (cnt - 1);
        if (FIRST) aptr[p] = X   + (size_t)g_tok[off + rr] * K + lc * 4;
        else       aptr[p] = g_h + (size_t)(off + rr) * K + lc * 4;
    }
    const float* bptr0 = W + (size_t)e * K * NTOT + (size_t)lr * NTOT + n0 + lc * 4;

    // STS byte offsets (swizzled)
    int aSts[4], bSts[4];
    #pragma unroll
    for (int p = 0; p < 4; ++p) {
        int row = lr + 32 * p;
        aSts[p] = row * 128 + ((lc ^ (row & 7)) << 4);
        int n4  = lc + 8 * p;
        bSts[p] = 16384 + lr * 512 + ((n4 ^ ((lr & 3) << 1)) << 4);
    }

    // LDS read bases (swizzled, conflict-free)
    const int rowbase = wm * 32 + g;
    const int aRdBase = rowbase * 128 + tig * 4;          // + ((2ks+h)^g)<<4 ; +1024 for +8 rows
    int bRd[8];
    #pragma unroll
    for (int nf = 0; nf < 8; ++nf) {
        int n4f = wn * 16 + nf * 2 + (g >> 2);
        bRd[nf] = 16384 + ((n4f ^ (tig << 1)) << 4) + (g & 3) * 4 + tig * 512;
    }

    float acc[2][8][4];
    #pragma unroll
    for (int i = 0; i < 2; ++i)
        #pragma unroll
        for (int j = 0; j < 8; ++j)
            #pragma unroll
            for (int r = 0; r < 4; ++r) acc[i][j][r] = 0.0f;

    // ---- prologue: chunk 0 -> stage ----
    {
        float4 pa[4], pb[4];
        #pragma unroll
        for (int p = 0; p < 4; ++p) pa[p] = *(const float4*)(aptr[p]);
        #pragma unroll
        for (int p = 0; p < 4; ++p) pb[p] = *(const float4*)(bptr0 + 32 * p);
        #pragma unroll
        for (int p = 0; p < 4; ++p) {
            uint4 u = { f2tf(pa[p].x), f2tf(pa[p].y), f2tf(pa[p].z), f2tf(pa[p].w) };
            *(uint4*)(sm + aSts[p]) = u;
        }
        #pragma unroll
        for (int p = 0; p < 4; ++p) {
            uint4 u = { f2tf(pb[p].x), f2tf(pb[p].y), f2tf(pb[p].z), f2tf(pb[p].w) };
            *(uint4*)(sm + bSts[p]) = u;
        }
    }
    __syncthreads();

    #pragma unroll 1
    for (int kt = 0; kt < KT; ++kt) {
        float4 pa[4], pb[4];
        const bool more = (kt + 1 < KT);
        if (more) {   // issue next chunk's LDGs before compute (latency overlap)
            #pragma unroll
            for (int p = 0; p < 4; ++p) pa[p] = *(const float4*)(aptr[p] + (kt + 1) * 32);
            #pragma unroll
            for (int p = 0; p < 4; ++p)
                pb[p] = *(const float4*)(bptr0 + (size_t)(kt + 1) * 32 * NTOT + 32 * p);
        }

        const char* base = sm;
        #pragma unroll
        for (int ks = 0; ks < 4; ++ks) {
            uint32_t A0[2][4];
            #pragma unroll
            for (int mf = 0; mf < 2; ++mf) {
                const int rb = aRdBase + mf * 2048;
                A0[mf][0] = *(const uint32_t*)(base + rb +        (((2 * ks)     ^ g) << 4));
                A0[mf][1] = *(const uint32_t*)(base + rb + 1024 + (((2 * ks)     ^ g) << 4));
                A0[mf][2] = *(const uint32_t*)(base + rb +        (((2 * ks + 1) ^ g) << 4));
                A0[mf][3] = *(const uint32_t*)(base + rb + 1024 + (((2 * ks + 1) ^ g) << 4));
            }
            #pragma unroll
            for (int nf = 0; nf < 8; ++nf) {
                uint32_t B0[2];
                B0[0] = *(const uint32_t*)(base + bRd[nf] + ks * 4096);
                B0[1] = *(const uint32_t*)(base + bRd[nf] + ks * 4096 + 2048);
                mma8(acc[0][nf], A0[0], B0);
                mma8(acc[1][nf], A0[1], B0);
            }
        }
        __syncthreads();                    // all reads of stage done

        if (more) {
            #pragma unroll
            for (int p = 0; p < 4; ++p) {
                uint4 u = { f2tf(pa[p].x), f2tf(pa[p].y), f2tf(pa[p].z), f2tf(pa[p].w) };
                *(uint4*)(sm + aSts[p]) = u;
            }
            #pragma unroll
            for (int p = 0; p < 4; ++p) {
                uint4 u = { f2tf(pb[p].x), f2tf(pb[p].y), f2tf(pb[p].z), f2tf(pb[p].w) };
                *(uint4*)(sm + bSts[p]) = u;
            }
            __syncthreads();                // stage refilled, visible to all
        }
    }

    // ---- epilogue: two passes of 64 rows through smem staging [64][132] ----
    float* stg = (float*)sm;
    #pragma unroll 1
    for (int pass = 0; pass < 2; ++pass) {
        if ((wm >> 1) == pass) {
            #pragma unroll
            for (int mf = 0; mf < 2; ++mf)
                #pragma unroll
                for (int nf = 0; nf < 8; ++nf) {
                    const int rl  = (wm & 1) * 32 + mf * 16 + g;
                    const int col = wn * 64 + nf * 8 + 2 * tig;
                    *(float2*)&stg[rl * 132 + col] =
                        make_float2(acc[mf][nf][0], acc[mf][nf][1]);
                    *(float2*)&stg[(rl + 8) * 132 + col] =
                        make_float2(acc[mf][nf][2], acc[mf][nf][3]);
                }
        }
        __syncthreads();
        {
            const int rl = tid >> 2;        // 0..63
            const int q  = tid & 3;         // 32-float quarter
            const int rm = m0 + pass * 64 + rl;
            if (rm < cnt) {
                float* dst;
                if (FIRST) dst = g_h + (size_t)(off + rm) * DFF + n0 + q * 32;
                else       dst = Y   + (size_t)g_tok[off + rm] * DOUT + n0 + q * 32;
                const float* bsrc = bias + (size_t)e * NTOT + n0 + q * 32;
                const float* s    = stg + rl * 132 + q * 32;
                #pragma unroll
                for (int j = 0; j < 8; ++j) {
                    float4 v  = *(const float4*)(s + 4 * j);
                    float4 bb = *(const float4*)(bsrc + 4 * j);
                    v.x += bb.x; v.y += bb.y; v.z += bb.z; v.w += bb.w;
                    if (FIRST) {
                        v.x = fmaxf(v.x, 0.f); v.y = fmaxf(v.y, 0.f);
                        v.z = fmaxf(v.z, 0.f); v.w = fmaxf(v.w, 0.f);
                    }
                    *(float4*)(dst + 4 * j) = v;
                }
            }
        }
        __syncthreads();
    }
}

// ===========================================================================
// kernel_launch: NO cudaFuncSetAttribute (dynamic smem <= 48KB default cap).
// ===========================================================================
extern "C" void kernel_launch(void* const* d_in, const int* in_sizes, int n_in,
                              void* d_out, int out_size)
{
    const float* x      = (const float*)d_in[0];
    const int*   groups = (const int*)  d_in[1];
    const float* W1     = (const float*)d_in[2];
    const float* b1     = (const float*)d_in[3];
    const float* W2     = (const float*)d_in[4];
    const float* b2     = (const float*)d_in[5];
    float*       out    = (float*)d_out;

    constexpr int SMEM_DYN = 64 * 132 * 4;   // 33792 B: >= 32KB stage, < 48KB cap

    route_kernel<<<1, 512>>>(groups);
    moe_mma_gemm<DIN, DFF, true ><<<dim3(DFF / 128, BTOK / 128, NSUB), 256, SMEM_DYN>>>(
        x, W1, b1, nullptr);
    moe_mma_gemm<DFF, DOUT, false><<<dim3(DOUT / 128, BTOK / 128, NSUB), 256, SMEM_DYN>>>(
        nullptr, W2, b2, out);
}